// round 8
// baseline (speedup 1.0000x reference)
#include <cuda_runtime.h>
#include <math.h>
#include <stdint.h>

#define SMEM_ROWS    1024      // 12 KB head-row buffer; freeze expected at ~293 rows
#define NTHREADS     256
#define NBLOCKS      592       // 4 blocks/SM * 148 SMs -> single wave
#define CHUNK_FLOATS 6144      // 24 KB TMA chunk; 6144 % 12 == 0 -> phase-0 aligned
#define CHUNK_BYTES  (CHUNK_FLOATS * 4)

__device__ __forceinline__ uint32_t smem_u32(const void* p) {
    uint32_t a;
    asm("{ .reg .u64 t; cvta.to.shared.u64 t, %1; cvt.u32.u64 %0, t; }"
        : "=r"(a) : "l"(p));
    return a;
}

// ---------------------------------------------------------------------------
// Single fused kernel. Every block redundantly runs the short serial prologue
// (deterministic, ~300 iters) into SMEM. The big constant region is written
// with cp.async.bulk (SMEM pattern buffer -> GMEM), bypassing the STG.128
// issue-cost wall and running at the LTS cap. Head + geometric transition
// rows are written by the remaining threads with normal stores (tiny).
//
// Recurrence (algebraically identical to reference, single rounding each):
//   u = 1-g+beff*S ; nI = I*u ; nS = fma(-beff*I,S,S) ; nR = fma(g,I,R)
// S monotone non-increasing => bitwise-stable over a 32-iter chunk (with
// 0<u<1) means frozen forever; tail is exactly geometric, then constant.
// ---------------------------------------------------------------------------
__global__ void __launch_bounds__(NTHREADS)
sir_fused_kernel(const float* __restrict__ x,
                 const float* __restrict__ bw,
                 const float* __restrict__ gw,
                 int steps, int total_elems,
                 float* __restrict__ out)
{
    __shared__ __align__(16) float s_rows[SMEM_ROWS * 3];   // 12 KB
    __shared__ __align__(16) float s_fill[CHUNK_FLOATS];    // 24 KB pattern buffer
    __shared__ int    s_nrows, s_r, s_cut;
    __shared__ float  s_S, s_Irec, s_A, s_Rinf;
    __shared__ double s_c;

    const int tid = threadIdx.x;

    // ---------------- Prologue: serial scan (thread 0 of every block) -----
    if (tid == 0) {
        float S = x[0], I = x[1], R = x[2];
        const float pop  = __fadd_rn(__fadd_rn(x[0], x[1]), x[2]);
        const float g    = gw[0];
        const float beff = (pop == 1.0f) ? bw[0] : __fdiv_rn(bw[0], pop);
        const float omg  = __fsub_rn(1.0f, g);

        s_rows[0] = S; s_rows[1] = I; s_rows[2] = R;

        int i = 1;
        for (int h = 0; h < 3 && i < steps; ++h, ++i) {     // head rows 1..3
            float u  = __fmaf_rn(beff, S, omg);
            float v  = __fmul_rn(beff, I);
            float nI = __fmul_rn(I, u);
            float nS = __fmaf_rn(-v, S, S);
            float nR = __fmaf_rn(g, I, R);
            S = nS; I = nI; R = nR;
            s_rows[3*i] = S; s_rows[3*i+1] = I; s_rows[3*i+2] = R;
        }

        bool frozen = false;
        const int cap = (steps < SMEM_ROWS) ? steps : SMEM_ROWS;
        for (; i + 32 <= cap; i += 32) {                    // 1 branch / 32 iters
            const float S0 = S;
            #pragma unroll
            for (int q = 0; q < 4; ++q) {
                float rbuf[24];
                #pragma unroll
                for (int k = 0; k < 8; ++k) {
                    float u  = __fmaf_rn(beff, S, omg);
                    float v  = __fmul_rn(beff, I);
                    float nI = __fmul_rn(I, u);
                    float nS = __fmaf_rn(-v, S, S);
                    float nR = __fmaf_rn(g, I, R);
                    S = nS; I = nI; R = nR;
                    rbuf[3*k] = S; rbuf[3*k+1] = I; rbuf[3*k+2] = R;
                }
                float4* p = reinterpret_cast<float4*>(s_rows + 3 * (i + 8 * q));
                p[0] = make_float4(rbuf[0],  rbuf[1],  rbuf[2],  rbuf[3]);
                p[1] = make_float4(rbuf[4],  rbuf[5],  rbuf[6],  rbuf[7]);
                p[2] = make_float4(rbuf[8],  rbuf[9],  rbuf[10], rbuf[11]);
                p[3] = make_float4(rbuf[12], rbuf[13], rbuf[14], rbuf[15]);
                p[4] = make_float4(rbuf[16], rbuf[17], rbuf[18], rbuf[19]);
                p[5] = make_float4(rbuf[20], rbuf[21], rbuf[22], rbuf[23]);
            }
            if (S == S0) {
                float u = __fmaf_rn(beff, S, omg);
                if (u < 1.0f && u > 0.0f) { i += 32; frozen = true; break; }
            }
        }

        if (frozen) {
            const int r_row = i - 1;
            const float  u  = __fmaf_rn(beff, S, omg);
            const double ud = (double)u;
            const double c  = log2(ud);                    // < 0
            const double Ad = (double)g * (double)I / (1.0 - ud);
            const double Rinf = (double)R + Ad;

            double mx = fmax((double)I, Ad);
            if (mx < 1e-300) mx = 1e-300;
            double t_d = (160.0 + log2(mx)) / (-c);        // u^t below any fp32 effect
            long long cut_ll = r_row + (long long)t_d + 8;
            long long cut4   = ((cut_ll + 3) / 4) * 4;     // multiple of 4 rows
            if (cut4 < (long long)i) cut4 = i;
            int cut = (cut4 > (long long)steps) ? steps : (int)cut4;

            s_nrows = i; s_r = r_row; s_cut = cut;
            s_S = S; s_Irec = I; s_A = (float)Ad; s_Rinf = (float)Rinf; s_c = c;
        } else {
            // Fallback: finish serially to gmem (redundant identical writes OK).
            s_nrows = i; s_r = steps - 1; s_cut = steps;
            for (; i < steps; ++i) {
                float u  = __fmaf_rn(beff, S, omg);
                float v  = __fmul_rn(beff, I);
                float nI = __fmul_rn(I, u);
                float nS = __fmaf_rn(-v, S, S);
                float nR = __fmaf_rn(g, I, R);
                S = nS; I = nI; R = nR;
                out[3*i] = S; out[3*i+1] = I; out[3*i+2] = R;
            }
            s_S = S; s_Irec = I; s_A = 0.0f; s_Rinf = R; s_c = 0.0;
        }
    }

    __syncthreads();

    const int gsize = gridDim.x * NTHREADS;
    const int gtid  = blockIdx.x * NTHREADS + tid;

    const int   nrows = s_nrows;
    const int   r     = s_r;
    const int   cut   = s_cut;
    const float S     = s_S;
    const float Irec  = s_Irec;
    const float A     = s_A;
    const float Rinf  = s_Rinf;
    const double c    = s_c;

    // ---- Build the 24 KB constant pattern buffer (phase 0 at offset 0) ----
    for (int idx = tid; idx < CHUNK_FLOATS; idx += NTHREADS) {
        const int m = idx % 3;
        s_fill[idx] = (m == 0) ? S : ((m == 1) ? 0.0f : Rinf);
    }
    __syncthreads();

    // ---- TMA bulk fill of the constant region [3*cut, total_elems) --------
    // eStart is a multiple of 12 floats (48 B); chunks are multiples of 48 B,
    // so every dst is 16B-aligned and every size a multiple of 16.
    const int eStart = 3 * cut;
    if (tid == 0 && eStart < total_elems) {
        asm volatile("fence.proxy.async.shared::cta;" ::: "memory");
        const uint32_t src = smem_u32(s_fill);
        for (int base = eStart + blockIdx.x * CHUNK_FLOATS;
             base < total_elems;
             base += gridDim.x * CHUNK_FLOATS) {
            int szf = total_elems - base;
            if (szf > CHUNK_FLOATS) szf = CHUNK_FLOATS;
            const uint32_t szb = (uint32_t)(szf & ~3) * 4;   // multiple of 16 B
            if (szb) {
                asm volatile(
                    "cp.async.bulk.global.shared::cta.bulk_group [%0], [%1], %2;"
                    :: "l"(out + base), "r"(src), "r"(szb) : "memory");
            }
        }
        asm volatile("cp.async.bulk.commit_group;" ::: "memory");
    }

    // ---- Head rows [0, nrows): smem -> gmem, coalesced ---------------------
    {
        const int nelem  = 3 * nrows;
        const int count4 = nelem / 4;
        const float4* srcp = reinterpret_cast<const float4*>(s_rows);
        float4*       dstp = reinterpret_cast<float4*>(out);
        for (int idx = gtid; idx < count4; idx += gsize)
            dstp[idx] = srcp[idx];
        for (int e = count4 * 4 + gtid; e < nelem; e += gsize)
            out[e] = s_rows[e];
    }

    // ---- Transition rows [nrows, cut): geometric closed form ---------------
    {
        const int eBeg = 3 * nrows;
        const int eEnd = 3 * cut;
        for (int e = eBeg + gtid; e < eEnd; e += gsize) {
            const int k    = e / 3;
            const int comp = e - 3 * k;
            const float p  = exp2f((float)((double)(k - r) * c));
            out[e] = (comp == 0) ? S
                   : (comp == 1) ? __fmul_rn(Irec, p)
                                 : __fmaf_rn(-A, p, Rinf);
        }
    }

    // ---- Scalar remainder (total_elems % 4 != 0 — not hit for steps=4M) ----
    if (gtid == 0) {
        const int e0 = (total_elems & ~3);
        for (int e = e0; e < total_elems; ++e) {
            const int k    = e / 3;
            const int comp = e - 3 * k;
            if (k >= cut)
                out[e] = (comp == 0) ? S : ((comp == 1) ? 0.0f : Rinf);
            else if (k >= nrows) {
                const float p = exp2f((float)((double)(k - r) * c));
                out[e] = (comp == 0) ? S
                       : (comp == 1) ? __fmul_rn(Irec, p)
                                     : __fmaf_rn(-A, p, Rinf);
            } else
                out[e] = s_rows[e];
        }
    }

    // ---- Drain bulk copies before SMEM is torn down ------------------------
    if (tid == 0 && eStart < total_elems) {
        asm volatile("cp.async.bulk.wait_group 0;" ::: "memory");
    }
}

extern "C" void kernel_launch(void* const* d_in, const int* in_sizes, int n_in,
                              void* d_out, int out_size)
{
    const float* x  = (const float*)d_in[0];
    const float* bw = (const float*)d_in[1];
    const float* gw = (const float*)d_in[2];
    float* out = (float*)d_out;

    const int steps = out_size / 3;

    sir_fused_kernel<<<NBLOCKS, NTHREADS>>>(x, bw, gw, steps, out_size, out);
}

// round 9
// speedup vs baseline: 1.0355x; 1.0355x over previous
#include <cuda_runtime.h>
#include <math.h>

#define SMEM_ROWS 1024     // 12 KB head-row buffer; freeze expected at ~290 rows
#define NTHREADS  256
#define NBLOCKS   592      // 4 blocks/SM * 148 SMs -> single co-resident wave

// ---------------------------------------------------------------------------
// Single fused kernel. Every block redundantly runs the short serial prologue
// (deterministic, ~290 iters) into its own SMEM; then all threads grid-stride
// over head rows (smem->gmem), geometric transition rows (closed form), and
// the constant tail (float4 stores; the 48 MB region is L2-write-bandwidth
// bound at ~3.5 TB/s — proven invariant across store shapes and TMA).
//
// Recurrence (single rounding per value):
//   u = 1-g+beff*S ; nI = I*u ; nS = fma(-beff*I,S,S) ; nR = fma(g,I,R)
// S is monotone non-increasing; bitwise-unchanged across a 32-iter chunk with
// 0<u<1 (contracting I) => frozen forever. Tail is then exactly geometric:
// I_m = Irec*u^m, R_m = Rinf - A*u^m; past `cut` (u^m below any fp32 effect)
// rows are the constant (S, 0, Rinf).
// ---------------------------------------------------------------------------
__global__ void __launch_bounds__(NTHREADS)
sir_fused_kernel(const float* __restrict__ x,
                 const float* __restrict__ bw,
                 const float* __restrict__ gw,
                 int steps, int total_elems,
                 float* __restrict__ out)
{
    __shared__ __align__(16) float s_rows[SMEM_ROWS * 3];   // 12 KB
    __shared__ int    s_nrows, s_r, s_cut;
    __shared__ float  s_S, s_Irec, s_A, s_Rinf;
    __shared__ double s_c;

    const int tid = threadIdx.x;

    // ---------------- Prologue: serial scan (thread 0 of every block) ------
    if (tid == 0) {
        float S = x[0], I = x[1], R = x[2];
        const float pop  = __fadd_rn(__fadd_rn(x[0], x[1]), x[2]);
        const float g    = gw[0];
        const float beff = (pop == 1.0f) ? bw[0] : __fdiv_rn(bw[0], pop);
        const float omg  = __fsub_rn(1.0f, g);

        s_rows[0] = S; s_rows[1] = I; s_rows[2] = R;

        int i = 1;
        for (int h = 0; h < 3 && i < steps; ++h, ++i) {     // head rows 1..3
            float u  = __fmaf_rn(beff, S, omg);
            float v  = __fmul_rn(beff, I);
            float nI = __fmul_rn(I, u);
            float nS = __fmaf_rn(-v, S, S);
            float nR = __fmaf_rn(g, I, R);
            S = nS; I = nI; R = nR;
            s_rows[3*i] = S; s_rows[3*i+1] = I; s_rows[3*i+2] = R;
        }

        bool frozen = false;
        const int cap = (steps < SMEM_ROWS) ? steps : SMEM_ROWS;
        // Slim chunked loop: scalar STS through an incrementing pointer,
        // one convergence branch per 32 iterations.
        for (; i + 32 <= cap; i += 32) {
            const float S0 = S;
            float* w = s_rows + 3 * i;
            #pragma unroll
            for (int k = 0; k < 32; ++k) {
                float u  = __fmaf_rn(beff, S, omg);
                float v  = __fmul_rn(beff, I);
                float nI = __fmul_rn(I, u);
                float nS = __fmaf_rn(-v, S, S);
                float nR = __fmaf_rn(g, I, R);
                S = nS; I = nI; R = nR;
                w[0] = S; w[1] = I; w[2] = R;
                w += 3;
            }
            if (S == S0) {
                float u = __fmaf_rn(beff, S, omg);
                if (u < 1.0f && u > 0.0f) { i += 32; frozen = true; break; }
            }
        }

        if (frozen) {
            const int r_row = i - 1;
            const float  u  = __fmaf_rn(beff, S, omg);
            const double ud = (double)u;
            const double c  = log2(ud);                    // < 0
            const double Ad = (double)g * (double)I / (1.0 - ud);
            const double Rinf = (double)R + Ad;

            double mx = fmax((double)I, Ad);
            if (mx < 1e-300) mx = 1e-300;
            double t_d = (160.0 + log2(mx)) / (-c);        // u^t below any fp32 effect
            long long cut_ll = r_row + (long long)t_d + 8;
            long long cut4   = ((cut_ll + 3) / 4) * 4;     // multiple of 4 rows
            if (cut4 < (long long)i) cut4 = i;
            int cut = (cut4 > (long long)steps) ? steps : (int)cut4;

            s_nrows = i; s_r = r_row; s_cut = cut;
            s_S = S; s_Irec = I; s_A = (float)Ad; s_Rinf = (float)Rinf; s_c = c;
        } else {
            // Fallback: finish serially to gmem (redundant identical writes OK).
            s_nrows = i; s_r = steps - 1; s_cut = steps;
            for (; i < steps; ++i) {
                float u  = __fmaf_rn(beff, S, omg);
                float v  = __fmul_rn(beff, I);
                float nI = __fmul_rn(I, u);
                float nS = __fmaf_rn(-v, S, S);
                float nR = __fmaf_rn(g, I, R);
                S = nS; I = nI; R = nR;
                out[3*i] = S; out[3*i+1] = I; out[3*i+2] = R;
            }
            s_S = S; s_Irec = I; s_A = 0.0f; s_Rinf = R; s_c = 0.0;
        }
    }

    __syncthreads();

    const int gsize = gridDim.x * NTHREADS;
    const int gtid  = blockIdx.x * NTHREADS + tid;

    const int   nrows = s_nrows;       // multiple of 4 when frozen
    const int   r     = s_r;
    const int   cut   = s_cut;
    const float S     = s_S;
    const float Irec  = s_Irec;
    const float A     = s_A;
    const float Rinf  = s_Rinf;
    const double c    = s_c;

    // ---- (a) Head rows [0, nrows): smem -> gmem, coalesced float4 ----------
    {
        const int nelem  = 3 * nrows;
        const int count4 = nelem / 4;
        const float4* srcp = reinterpret_cast<const float4*>(s_rows);
        float4*       dstp = reinterpret_cast<float4*>(out);
        for (int idx = gtid; idx < count4; idx += gsize)
            dstp[idx] = srcp[idx];
        for (int e = count4 * 4 + gtid; e < nelem; e += gsize)   // tiny-steps remainder
            out[e] = s_rows[e];
    }

    // ---- (b) Transition rows [nrows, cut): geometric closed form -----------
    {
        const int eBeg = 3 * nrows;
        const int eEnd = 3 * cut;
        for (int e = eBeg + gtid; e < eEnd; e += gsize) {
            const int k    = e / 3;
            const int comp = e - 3 * k;
            const float p  = exp2f((float)((double)(k - r) * c));
            out[e] = (comp == 0) ? S
                   : (comp == 1) ? __fmul_rn(Irec, p)
                                 : __fmaf_rn(-A, p, Rinf);
        }
    }

    // ---- (c) Constant region [cut, steps): (S, 0, Rinf) --------------------
    // 1 float4/thread-iteration grid-stride (at the L2-write cap).
    // 3*cut % 12 == 0 -> start4 is a valid float4 index; phase = j % 3,
    // strength-reduced: gsize % 3 == 1, so phase rotates +1 per iteration.
    {
        const int n4     = total_elems / 4;
        const int start4 = (3 * cut) / 4;

        const float4 P0 = make_float4(S,    0.0f, Rinf, S);
        const float4 P1 = make_float4(0.0f, Rinf, S,    0.0f);
        const float4 P2 = make_float4(Rinf, S,    0.0f, Rinf);

        float4* out4 = reinterpret_cast<float4*>(out);
        int j  = start4 + gtid;
        int ph = j % 3;
        const int phinc = gsize % 3;                 // 592*256 % 3 == 1
        for (; j < n4; j += gsize) {
            out4[j] = (ph == 0) ? P0 : ((ph == 1) ? P1 : P2);
            ph += phinc; if (ph >= 3) ph -= 3;
        }

        // Scalar remainder (total_elems % 4 != 0 — not hit for steps = 4M).
        if (gtid == 0) {
            for (int e = n4 * 4; e < total_elems; ++e) {
                const int k    = e / 3;
                const int comp = e - 3 * k;
                if (k >= cut)
                    out[e] = (comp == 0) ? S : ((comp == 1) ? 0.0f : Rinf);
                else if (k >= nrows) {
                    const float p = exp2f((float)((double)(k - r) * c));
                    out[e] = (comp == 0) ? S
                           : (comp == 1) ? __fmul_rn(Irec, p)
                                         : __fmaf_rn(-A, p, Rinf);
                } else
                    out[e] = s_rows[e];
            }
        }
    }
}

extern "C" void kernel_launch(void* const* d_in, const int* in_sizes, int n_in,
                              void* d_out, int out_size)
{
    const float* x  = (const float*)d_in[0];
    const float* bw = (const float*)d_in[1];
    const float* gw = (const float*)d_in[2];
    float* out = (float*)d_out;

    const int steps = out_size / 3;

    sir_fused_kernel<<<NBLOCKS, NTHREADS>>>(x, bw, gw, steps, out_size, out);
}